// round 16
// baseline (speedup 1.0000x reference)
#include <cuda_runtime.h>
#include <cstdint>

#define Bn_ 4
#define Lseq 4096
#define DM 96
#define DI 96
#define DS 16
#define DTR 6
#define CDIM 38
#define CH 64
#define NCH (Lseq / CH)        // 64
#define NCHAIN 24576           // 16 * 96 * 16
#define L2E 1.44269504f

__device__ __forceinline__ float ex2f(float x) {
    float r;
    asm("ex2.approx.f32 %0, %1;" : "=f"(r) : "f"(x));
    return r;
}

// -------------------- scratch --------------------
__device__ float g_xz[Bn_ * Lseq * 192];
__device__ float g_xraw[Bn_ * DI * Lseq];
__device__ float g_xc[Bn_ * DI * Lseq];
__device__ float g_xcT[Bn_ * DI * Lseq];
__device__ float g_b4[16 * (Lseq / 4) * 16 * 4];  // [bk][l/4][n][4]
__device__ float g_c4[16 * (Lseq / 4) * 16 * 4];  // [bk][l/4][n][4]
__device__ float g_deltaT[16 * DI * Lseq];        // [bk][d][l]
__device__ float g_duT[16 * DI * Lseq];           // [bk][d][l] = delta*u (scan order)
__device__ float g_ysd[16 * DI * Lseq];           // scan out [bk][d][p] (spatial hw order)
__device__ float g_yg[Bn_ * Lseq * DI];
__device__ float g_hend[NCH * NCHAIN];
__device__ float g_pprod[NCH * NCHAIN];
__device__ float g_hinit[NCH * NCHAIN];

// -------------------- in_proj GEMM fused with split+transpose --------------------
__global__ void gemm_in_proj(const float* __restrict__ A, const float* __restrict__ Bm,
                             float* __restrict__ C, float* __restrict__ xraw) {
    __shared__ __align__(16) float As[32][68];
    __shared__ __align__(16) float Bs[32][68];
    __shared__ float Tr[64][65];
    const int N = 192, K = 96;
    int tid = threadIdx.x;
    int tx = tid & 15, ty = tid >> 4;
    int rowBase = blockIdx.y * 64;
    int colBase = blockIdx.x * 64;
    float acc[4][4];
#pragma unroll
    for (int i = 0; i < 4; i++)
#pragma unroll
        for (int j = 0; j < 4; j++) acc[i][j] = 0.f;

    for (int k0 = 0; k0 < K; k0 += 32) {
#pragma unroll
        for (int pass = 0; pass < 8; pass++) {
            int m = (tid >> 5) + pass * 8;
            int kk = tid & 31;
            As[kk][m] = A[(size_t)(rowBase + m) * K + k0 + kk];
            Bs[kk][m] = Bm[(size_t)(colBase + m) * K + k0 + kk];
        }
        __syncthreads();
#pragma unroll
        for (int kk = 0; kk < 32; kk++) {
            float4 a4 = *reinterpret_cast<const float4*>(&As[kk][ty * 4]);
            float4 b4 = *reinterpret_cast<const float4*>(&Bs[kk][tx * 4]);
            float av[4] = {a4.x, a4.y, a4.z, a4.w};
            float bv[4] = {b4.x, b4.y, b4.z, b4.w};
#pragma unroll
            for (int i = 0; i < 4; i++)
#pragma unroll
                for (int j = 0; j < 4; j++) acc[i][j] = fmaf(av[i], bv[j], acc[i][j]);
        }
        __syncthreads();
    }
    int col = colBase + tx * 4;
#pragma unroll
    for (int i = 0; i < 4; i++) {
        int row = rowBase + ty * 4 + i;
        *reinterpret_cast<float4*>(&C[(size_t)row * N + col]) =
            make_float4(acc[i][0], acc[i][1], acc[i][2], acc[i][3]);
    }
    if (colBase < 96) {
#pragma unroll
        for (int i = 0; i < 4; i++)
#pragma unroll
            for (int j = 0; j < 4; j++) Tr[tx * 4 + j][ty * 4 + i] = acc[i][j];
        __syncthreads();
        for (int idx = tid; idx < 4096; idx += 256) {
            int dl = idx >> 6, pl = idx & 63;
            int dg = colBase + dl;
            if (dg < 96) {
                int row = rowBase + pl;
                int bb = row >> 12, p = row & 4095;
                xraw[((size_t)bb * DI + dg) * Lseq + p] = Tr[dl][pl];
            }
        }
    }
}

// -------------------- generic GEMM C = A * B^T (out_proj) --------------------
__global__ void gemm_abt(const float* __restrict__ A, const float* __restrict__ Bm,
                         float* __restrict__ C, int M, int N, int K) {
    __shared__ __align__(16) float As[32][68];
    __shared__ __align__(16) float Bs[32][68];
    int tid = threadIdx.x;
    int tx = tid & 15, ty = tid >> 4;
    int rowBase = blockIdx.y * 64;
    int colBase = blockIdx.x * 64;
    float acc[4][4];
#pragma unroll
    for (int i = 0; i < 4; i++)
#pragma unroll
        for (int j = 0; j < 4; j++) acc[i][j] = 0.f;

    for (int k0 = 0; k0 < K; k0 += 32) {
#pragma unroll
        for (int pass = 0; pass < 8; pass++) {
            int m = (tid >> 5) + pass * 8;
            int kk = tid & 31;
            As[kk][m] = A[(size_t)(rowBase + m) * K + k0 + kk];
            int nn = colBase + m;
            Bs[kk][m] = (nn < N) ? Bm[(size_t)nn * K + k0 + kk] : 0.f;
        }
        __syncthreads();
#pragma unroll
        for (int kk = 0; kk < 32; kk++) {
            float4 a4 = *reinterpret_cast<const float4*>(&As[kk][ty * 4]);
            float4 b4 = *reinterpret_cast<const float4*>(&Bs[kk][tx * 4]);
            float av[4] = {a4.x, a4.y, a4.z, a4.w};
            float bv[4] = {b4.x, b4.y, b4.z, b4.w};
#pragma unroll
            for (int i = 0; i < 4; i++)
#pragma unroll
                for (int j = 0; j < 4; j++) acc[i][j] = fmaf(av[i], bv[j], acc[i][j]);
        }
        __syncthreads();
    }
    int col = colBase + tx * 4;
    if (col < N) {
#pragma unroll
        for (int i = 0; i < 4; i++) {
            int row = rowBase + ty * 4 + i;
            *reinterpret_cast<float4*>(&C[(size_t)row * N + col]) =
                make_float4(acc[i][0], acc[i][1], acc[i][2], acc[i][3]);
        }
    }
}

// -------------------- depthwise conv3x3 + SiLU --------------------
__global__ void conv_silu(const float* __restrict__ xraw, const float* __restrict__ cw,
                          const float* __restrict__ cb, float* __restrict__ xc,
                          float* __restrict__ xcT) {
    __shared__ float sin_[64][65];
    __shared__ float sout[64][65];
    int bd = blockIdx.x;
    int d = bd % DI;
    const float* plane = xraw + (size_t)bd * Lseq;
    int tid = threadIdx.x;
    for (int i = tid; i < 4096; i += 256) sin_[i >> 6][i & 63] = plane[i];
    float w9[9];
#pragma unroll
    for (int j = 0; j < 9; j++) w9[j] = cw[d * 9 + j];
    float bias = cb[d];
    __syncthreads();
    for (int i = tid; i < 4096; i += 256) {
        int h = i >> 6, w = i & 63;
        float acc = bias;
#pragma unroll
        for (int di = -1; di <= 1; di++) {
#pragma unroll
            for (int dj = -1; dj <= 1; dj++) {
                int hh = h + di, ww = w + dj;
                if (hh >= 0 && hh < 64 && ww >= 0 && ww < 64)
                    acc = fmaf(w9[(di + 1) * 3 + dj + 1], sin_[hh][ww], acc);
            }
        }
        float s = acc / (1.f + __expf(-acc));
        sout[h][w] = s;
        xc[(size_t)bd * Lseq + i] = s;
    }
    __syncthreads();
    for (int i = tid; i < 4096; i += 256) {
        int w = i >> 6, h = i & 63;
        xcT[(size_t)bd * Lseq + i] = sout[h][w];
    }
}

// -------------------- x_proj + dt_proj + softplus fused --------------------
#define LT 64
#define WROWS 40
__device__ __forceinline__ float softplusf(float x) {
    return (x > 15.f) ? x : log1pf(__expf(x));
}

__global__ void xproj_kernel(const float* __restrict__ xc, const float* __restrict__ xcT,
                             const float* __restrict__ xpw, const float* __restrict__ dtw,
                             const float* __restrict__ dtb,
                             float* __restrict__ b4, float* __restrict__ c4,
                             float* __restrict__ deltaT, float* __restrict__ duT) {
    __shared__ __align__(16) float Ws[WROWS * 96];   // zero-padded; aliased as sBc after GEMM
    __shared__ float Us[96][LT];
    __shared__ float Dts[DTR][LT];
    __shared__ float Wdt[96 * DTR];
    __shared__ float Bdt[96];
    int bk = blockIdx.y;
    int b = bk >> 2, k = bk & 3;
    int l0 = blockIdx.x * LT;
    int tid = threadIdx.x;
    for (int i = tid; i < WROWS * 96; i += 256)
        Ws[i] = (i < CDIM * 96) ? xpw[k * CDIM * 96 + i] : 0.f;
    for (int i = tid; i < 96 * DTR; i += 256) Wdt[i] = dtw[k * 96 * DTR + i];
    if (tid < 96) Bdt[tid] = dtb[k * 96 + tid];
    const float* src = ((k & 1) ? xcT : xc) + (size_t)b * DI * Lseq;
    bool rev = (k >= 2);
    for (int i = tid; i < 96 * LT; i += 256) {
        int e = i >> 6, li = i & 63;
        int l = l0 + li;
        Us[e][li] = src[(size_t)e * Lseq + (rev ? (Lseq - 1 - l) : l)];
    }
    __syncthreads();
    int lx = tid & 31, cy = tid >> 5;
    float acc[5][2];
#pragma unroll
    for (int j = 0; j < 5; j++) { acc[j][0] = 0.f; acc[j][1] = 0.f; }
#pragma unroll 2
    for (int e4 = 0; e4 < 96; e4 += 4) {
        float4 wv[5];
#pragma unroll
        for (int j = 0; j < 5; j++)
            wv[j] = *reinterpret_cast<const float4*>(&Ws[(cy + 8 * j) * 96 + e4]);
#pragma unroll
        for (int q = 0; q < 4; q++) {
            int e = e4 + q;
            float u0 = Us[e][lx];
            float u1 = Us[e][lx + 32];
#pragma unroll
            for (int j = 0; j < 5; j++) {
                float w = (&wv[j].x)[q];
                acc[j][0] = fmaf(w, u0, acc[j][0]);
                acc[j][1] = fmaf(w, u1, acc[j][1]);
            }
        }
    }
    __syncthreads();   // Ws reads complete; alias as sBc
    float (*sBc)[33] = reinterpret_cast<float (*)[33]>(&Ws[0]);
#pragma unroll
    for (int j = 0; j < 5; j++) {
        int c = cy + 8 * j;
        if (c < DTR) {
            Dts[c][lx] = acc[j][0];
            Dts[c][lx + 32] = acc[j][1];
        } else if (c < CDIM) {
            int cc = c - DTR;                       // 0..31
            int slot = (cc < DS) ? (2 * cc) : (2 * (cc - DS) + 1);
            sBc[lx][slot] = acc[j][0];
            sBc[lx + 32][slot] = acc[j][1];
        }
    }
    __syncthreads();
    // quad-packed copy-out: B4/C4 [l/4][n][4]
    size_t qbase = ((size_t)bk * (Lseq / 4) + (l0 >> 2)) * 64;   // 16 l4 * 16 n * 4 j per tile
#pragma unroll
    for (int pass = 0; pass < 4; pass++) {
        int idx = pass * 256 + tid;              // 0..1023
        int l4 = idx >> 6, n = (idx >> 2) & 15, j = idx & 3;
        int l = l4 * 4 + j;
        b4[qbase + idx] = sBc[l][2 * n];
        c4[qbase + idx] = sBc[l][2 * n + 1];
    }
    // delta stage: delta + du (u still live in Us)
#pragma unroll
    for (int o = 0; o < 24; o++) {
        int idx = o * 256 + tid;
        int li = idx & 63, dd = idx >> 6;
        float a = Bdt[dd];
#pragma unroll
        for (int r = 0; r < DTR; r++) a = fmaf(Dts[r][li], Wdt[dd * DTR + r], a);
        float sp = softplusf(a);
        size_t off = ((size_t)bk * DI + dd) * Lseq + l0 + li;
        deltaT[off] = sp;
        duT[off] = sp * Us[dd][li];
    }
}

// -------------------- chunked selective scan --------------------
// scanA: 4 states/lane (warp = 8d x 4 n-groups); chain index bk*1536 + d*16 + n

__global__ void __launch_bounds__(256, 6)
scanA_kernel(const float* __restrict__ deltaT, const float* __restrict__ duT,
             const float* __restrict__ b4,
             const float* __restrict__ A_logs,
             float* __restrict__ hend, float* __restrict__ pprod) {
    int w = blockIdx.x * 8 + (threadIdx.x >> 5);   // 12288 warps
    int lane = threadIdx.x & 31;
    int bk = w / (12 * NCH);
    int rem = w % (12 * NCH);
    int chunk = rem / 12;
    int dg = rem % 12;
    int k = bk & 3;
    int ng = lane & 3;        // states n = ng*4 + j
    int dq = lane >> 2;       // 0..7
    int d = dg * 8 + dq;
    float Avb = -__expf(A_logs[(k * DI + d) * DS + ng * 4]) * L2E;   // A for j=0
    int l0 = chunk * CH;

    const float4* drow = reinterpret_cast<const float4*>(deltaT + ((size_t)bk * DI + d) * Lseq + l0);
    const float4* durow = reinterpret_cast<const float4*>(duT + ((size_t)bk * DI + d) * Lseq + l0);
    const float4* brow = reinterpret_cast<const float4*>(b4) + ((size_t)bk * (Lseq / 4) + (l0 >> 2)) * 16 + ng * 4;

    float h0 = 0.f, h1 = 0.f, h2 = 0.f, h3 = 0.f, S = 0.f;
#pragma unroll 2
    for (int g = 0; g < CH / 4; g++) {
        float4 dl4 = __ldg(drow + g);
        float4 du4 = __ldg(durow + g);
        float4 Bq0 = __ldg(brow + g * 16);
        float4 Bq1 = __ldg(brow + g * 16 + 1);
        float4 Bq2 = __ldg(brow + g * 16 + 2);
        float4 Bq3 = __ldg(brow + g * 16 + 3);
        S += (dl4.x + dl4.y) + (dl4.z + dl4.w);
        float dls[4] = {dl4.x, dl4.y, dl4.z, dl4.w};
        float dus[4] = {du4.x, du4.y, du4.z, du4.w};
        float B0s[4] = {Bq0.x, Bq0.y, Bq0.z, Bq0.w};
        float B1s[4] = {Bq1.x, Bq1.y, Bq1.z, Bq1.w};
        float B2s[4] = {Bq2.x, Bq2.y, Bq2.z, Bq2.w};
        float B3s[4] = {Bq3.x, Bq3.y, Bq3.z, Bq3.w};
#pragma unroll
        for (int j = 0; j < 4; j++) {
            float dA = ex2f(dls[j] * Avb);
            float r = ex2f(-dls[j] * L2E);
            float duv = dus[j];
            h0 = fmaf(h0, dA, duv * B0s[j]);
            dA *= r;
            h1 = fmaf(h1, dA, duv * B1s[j]);
            dA *= r;
            h2 = fmaf(h2, dA, duv * B2s[j]);
            dA *= r;
            h3 = fmaf(h3, dA, duv * B3s[j]);
        }
    }
    int cbase = chunk * NCHAIN + bk * 1536 + d * 16 + ng * 4;
    *reinterpret_cast<float4*>(hend + cbase) = make_float4(h0, h1, h2, h3);
    float pp0 = ex2f(Avb * S);
    float rs = ex2f(-S * L2E);
    float pp1 = pp0 * rs;
    float pp2 = pp1 * rs;
    float pp3 = pp2 * rs;
    *reinterpret_cast<float4*>(pprod + cbase) = make_float4(pp0, pp1, pp2, pp3);
}

__global__ void scanB_kernel(const float* __restrict__ hend, const float* __restrict__ pprod,
                             float* __restrict__ hinit) {
    int chain = blockIdx.x * 256 + threadIdx.x;
    float H = 0.f;
#pragma unroll 8
    for (int c = 0; c < NCH; c++) {
        int idx = c * NCHAIN + chain;
        hinit[idx] = H;
        H = fmaf(H, pprod[idx], hend[idx]);
    }
}

// scanC: 2 states/lane (warp = 4d x 8n), R15 form
__global__ void __launch_bounds__(256, 6)
scanC_kernel(const float* __restrict__ deltaT, const float* __restrict__ duT,
             const float* __restrict__ b4, const float* __restrict__ c4,
             const float* __restrict__ A_logs,
             const float* __restrict__ hinit, float* __restrict__ ysd) {
    int w = blockIdx.x * 8 + (threadIdx.x >> 5);   // 24576 warps
    int lane = threadIdx.x & 31;
    int bk = w / (24 * NCH);
    int rem = w % (24 * NCH);
    int chunk = rem / 24;
    int dg = rem % 24;
    int k = bk & 3;
    int nq = lane & 7;
    int dq = lane >> 3;
    int d = dg * 4 + dq;
    float Av0 = -__expf(A_logs[(k * DI + d) * DS + nq]) * L2E;
    float Av1 = -__expf(A_logs[(k * DI + d) * DS + nq + 8]) * L2E;
    int l0 = chunk * CH;

    const float4* drow = reinterpret_cast<const float4*>(deltaT + ((size_t)bk * DI + d) * Lseq + l0);
    const float4* durow = reinterpret_cast<const float4*>(duT + ((size_t)bk * DI + d) * Lseq + l0);
    const float4* brow = reinterpret_cast<const float4*>(b4) + ((size_t)bk * (Lseq / 4) + (l0 >> 2)) * 16 + nq;
    const float4* crow = reinterpret_cast<const float4*>(c4) + ((size_t)bk * (Lseq / 4) + (l0 >> 2)) * 16 + nq;

    int pstart, pstep;
    if (k == 0)      { pstart = l0;            pstep = 1;   }
    else if (k == 1) { pstart = chunk;         pstep = 64;  }
    else if (k == 2) { pstart = Lseq - 1 - l0; pstep = -1;  }
    else             { pstart = 4095 - chunk;  pstep = -64; }
    float* ybase = ysd + ((size_t)bk * DI + d) * Lseq + pstart;
    int ridx = ((nq & 4) ? 2 : 0) + ((nq & 2) ? 1 : 0);
    bool writer = ((nq & 1) == 0);

    int cbase = chunk * NCHAIN + bk * 1536 + d * 16 + nq;
    float h0 = hinit[cbase];
    float h1 = hinit[cbase + 8];
    const unsigned FULL = 0xffffffffu;

#pragma unroll 2
    for (int g = 0; g < CH / 4; g++) {
        float4 dl4 = __ldg(drow + g);
        float4 du4 = __ldg(durow + g);
        float4 B0 = __ldg(brow + g * 16);
        float4 B1 = __ldg(brow + g * 16 + 8);
        float4 C0 = __ldg(crow + g * 16);
        float4 C1 = __ldg(crow + g * 16 + 8);
        float dls[4] = {dl4.x, dl4.y, dl4.z, dl4.w};
        float dus[4] = {du4.x, du4.y, du4.z, du4.w};
        float B0s[4] = {B0.x, B0.y, B0.z, B0.w};
        float B1s[4] = {B1.x, B1.y, B1.z, B1.w};
        float C0s[4] = {C0.x, C0.y, C0.z, C0.w};
        float C1s[4] = {C1.x, C1.y, C1.z, C1.w};
        float acc[4];
#pragma unroll
        for (int j = 0; j < 4; j++) {
            float dA0 = ex2f(dls[j] * Av0);
            h0 = fmaf(h0, dA0, dus[j] * B0s[j]);
            float dA1 = ex2f(dls[j] * Av1);
            h1 = fmaf(h1, dA1, dus[j] * B1s[j]);
            float p = h0 * C0s[j];
            acc[j] = fmaf(h1, C1s[j], p);
        }
        bool up4 = (nq & 4);
#pragma unroll
        for (int j = 0; j < 2; j++) {
            float mine = up4 ? acc[j + 2] : acc[j];
            float oth  = up4 ? acc[j] : acc[j + 2];
            acc[j] = mine + __shfl_xor_sync(FULL, oth, 4);
        }
        {
            bool up2 = (nq & 2);
            float mine = up2 ? acc[1] : acc[0];
            float oth  = up2 ? acc[0] : acc[1];
            acc[0] = mine + __shfl_xor_sync(FULL, oth, 2);
        }
        acc[0] += __shfl_xor_sync(FULL, acc[0], 1);
        if (writer) ybase[(g * 4 + ridx) * pstep] = acc[0];
    }
}

// -------------------- combine 4 dirs + D*u skip + LayerNorm + SiLU gate --------------------
__global__ void combine_ln_gate(const float* __restrict__ ysd, const float* __restrict__ xc,
                                const float* __restrict__ dsp, const float* __restrict__ xz,
                                const float* __restrict__ nw, const float* __restrict__ nb,
                                float* __restrict__ yg) {
    __shared__ float s[96][33];
    int b = blockIdx.y;
    int p0 = blockIdx.x * 32;
    int tid = threadIdx.x;
    int px = tid & 31, drow = tid >> 5;
    const float* base = ysd + (size_t)(b * 4) * DI * Lseq + p0 + px;
#pragma unroll
    for (int j = 0; j < 12; j++) {
        int dd = drow + j * 8;
        const float* r = base + (size_t)dd * Lseq;
        float dsum = dsp[dd] + dsp[DI + dd] + dsp[2 * DI + dd] + dsp[3 * DI + dd];
        float xcv = xc[((size_t)b * DI + dd) * Lseq + p0 + px];
        float v = r[0] + r[DI * Lseq] + r[2 * DI * Lseq] + r[3 * DI * Lseq];
        s[dd][px] = fmaf(dsum, xcv, v);
    }
    __syncthreads();
    int p = tid >> 3, rr = tid & 7;
    float s1 = 0.f, s2 = 0.f;
#pragma unroll
    for (int m = 0; m < 12; m++) {
        float v = s[rr + m * 8][p];
        s1 += v;
        s2 = fmaf(v, v, s2);
    }
#pragma unroll
    for (int o = 4; o >= 1; o >>= 1) {
        s1 += __shfl_xor_sync(0xffffffffu, s1, o);
        s2 += __shfl_xor_sync(0xffffffffu, s2, o);
    }
    float mu = s1 * (1.f / 96.f);
    float var = s2 * (1.f / 96.f) - mu * mu;
    float rinv = rsqrtf(var + 1e-5f);
    size_t rowout = ((size_t)b * Lseq + p0 + p);
#pragma unroll
    for (int m = 0; m < 12; m++) {
        int dd = rr + m * 8;
        float v = s[dd][p];
        float yn = (v - mu) * rinv * nw[dd] + nb[dd];
        float zv = xz[rowout * 192 + 96 + dd];
        yg[rowout * DI + dd] = yn * (zv / (1.f + __expf(-zv)));
    }
}

// -------------------- host launcher --------------------
extern "C" void kernel_launch(void* const* d_in, const int* in_sizes, int n_in,
                              void* d_out, int out_size) {
    const float* x     = (const float*)d_in[0];
    const float* inw   = (const float*)d_in[1];
    const float* convw = (const float*)d_in[2];
    const float* convb = (const float*)d_in[3];
    const float* xpw   = (const float*)d_in[4];
    const float* dtw   = (const float*)d_in[5];
    const float* dtb   = (const float*)d_in[6];
    const float* alog  = (const float*)d_in[7];
    const float* dsp   = (const float*)d_in[8];
    const float* nw    = (const float*)d_in[9];
    const float* nb    = (const float*)d_in[10];
    const float* ow    = (const float*)d_in[11];
    float* out = (float*)d_out;

    float *xz, *xraw, *xc, *xcT, *b4, *c4, *deltaT, *duT, *ysd, *yg, *hend, *pprod, *hinit;
    cudaGetSymbolAddress((void**)&xz, g_xz);
    cudaGetSymbolAddress((void**)&xraw, g_xraw);
    cudaGetSymbolAddress((void**)&xc, g_xc);
    cudaGetSymbolAddress((void**)&xcT, g_xcT);
    cudaGetSymbolAddress((void**)&b4, g_b4);
    cudaGetSymbolAddress((void**)&c4, g_c4);
    cudaGetSymbolAddress((void**)&deltaT, g_deltaT);
    cudaGetSymbolAddress((void**)&duT, g_duT);
    cudaGetSymbolAddress((void**)&ysd, g_ysd);
    cudaGetSymbolAddress((void**)&yg, g_yg);
    cudaGetSymbolAddress((void**)&hend, g_hend);
    cudaGetSymbolAddress((void**)&pprod, g_pprod);
    cudaGetSymbolAddress((void**)&hinit, g_hinit);

    gemm_in_proj<<<dim3(3, 256), 256>>>(x, inw, xz, xraw);
    conv_silu<<<Bn_ * DI, 256>>>(xraw, convw, convb, xc, xcT);
    xproj_kernel<<<dim3(Lseq / LT, 16), 256>>>(xc, xcT, xpw, dtw, dtb, b4, c4, deltaT, duT);
    scanA_kernel<<<16 * 12 * NCH / 8, 256>>>(deltaT, duT, b4, alog, hend, pprod);
    scanB_kernel<<<NCHAIN / 256, 256>>>(hend, pprod, hinit);
    scanC_kernel<<<16 * 24 * NCH / 8, 256>>>(deltaT, duT, b4, c4, alog, hinit, ysd);
    combine_ln_gate<<<dim3(Lseq / 32, Bn_), 256>>>(ysd, xc, dsp, xz, nw, nb, yg);
    gemm_abt<<<dim3(2, 256), 256>>>(yg, ow, out, Bn_ * Lseq, 96, 96);
}

// round 17
// speedup vs baseline: 1.0480x; 1.0480x over previous
#include <cuda_runtime.h>
#include <cstdint>

#define Bn_ 4
#define Lseq 4096
#define DM 96
#define DI 96
#define DS 16
#define DTR 6
#define CDIM 38
#define CH 64
#define NCH (Lseq / CH)        // 64
#define NCHAIN 24576           // 16 * 96 * 16
#define L2E 1.44269504f

__device__ __forceinline__ float ex2f(float x) {
    float r;
    asm("ex2.approx.f32 %0, %1;" : "=f"(r) : "f"(x));
    return r;
}

// -------------------- scratch --------------------
__device__ float g_xz[Bn_ * Lseq * 192];
__device__ float g_xraw[Bn_ * DI * Lseq];
__device__ float g_xc[Bn_ * DI * Lseq];
__device__ float g_xcT[Bn_ * DI * Lseq];
__device__ float g_b4[16 * (Lseq / 4) * 16 * 4];  // [bk][l/4][n][4]
__device__ float g_c4[16 * (Lseq / 4) * 16 * 4];  // [bk][l/4][n][4]
__device__ float g_deltaT[16 * DI * Lseq];        // [bk][d][l]
__device__ float g_duT[16 * DI * Lseq];           // [bk][d][l] = delta*u (scan order)
__device__ float g_ysd[16 * DI * Lseq];           // scan out [bk][d][p] (spatial hw order)
__device__ float g_yg[Bn_ * Lseq * DI];
__device__ float g_hend[NCH * NCHAIN];
__device__ float g_pprod[NCH * NCHAIN];
__device__ float g_hinit[NCH * NCHAIN];

// -------------------- in_proj GEMM fused with split+transpose --------------------
__global__ void gemm_in_proj(const float* __restrict__ A, const float* __restrict__ Bm,
                             float* __restrict__ C, float* __restrict__ xraw) {
    __shared__ __align__(16) float As[32][68];
    __shared__ __align__(16) float Bs[32][68];
    __shared__ float Tr[64][65];
    const int N = 192, K = 96;
    int tid = threadIdx.x;
    int tx = tid & 15, ty = tid >> 4;
    int rowBase = blockIdx.y * 64;
    int colBase = blockIdx.x * 64;
    float acc[4][4];
#pragma unroll
    for (int i = 0; i < 4; i++)
#pragma unroll
        for (int j = 0; j < 4; j++) acc[i][j] = 0.f;

    for (int k0 = 0; k0 < K; k0 += 32) {
#pragma unroll
        for (int pass = 0; pass < 8; pass++) {
            int m = (tid >> 5) + pass * 8;
            int kk = tid & 31;
            As[kk][m] = A[(size_t)(rowBase + m) * K + k0 + kk];
            Bs[kk][m] = Bm[(size_t)(colBase + m) * K + k0 + kk];
        }
        __syncthreads();
#pragma unroll
        for (int kk = 0; kk < 32; kk++) {
            float4 a4 = *reinterpret_cast<const float4*>(&As[kk][ty * 4]);
            float4 b4 = *reinterpret_cast<const float4*>(&Bs[kk][tx * 4]);
            float av[4] = {a4.x, a4.y, a4.z, a4.w};
            float bv[4] = {b4.x, b4.y, b4.z, b4.w};
#pragma unroll
            for (int i = 0; i < 4; i++)
#pragma unroll
                for (int j = 0; j < 4; j++) acc[i][j] = fmaf(av[i], bv[j], acc[i][j]);
        }
        __syncthreads();
    }
    int col = colBase + tx * 4;
#pragma unroll
    for (int i = 0; i < 4; i++) {
        int row = rowBase + ty * 4 + i;
        *reinterpret_cast<float4*>(&C[(size_t)row * N + col]) =
            make_float4(acc[i][0], acc[i][1], acc[i][2], acc[i][3]);
    }
    if (colBase < 96) {
#pragma unroll
        for (int i = 0; i < 4; i++)
#pragma unroll
            for (int j = 0; j < 4; j++) Tr[tx * 4 + j][ty * 4 + i] = acc[i][j];
        __syncthreads();
        for (int idx = tid; idx < 4096; idx += 256) {
            int dl = idx >> 6, pl = idx & 63;
            int dg = colBase + dl;
            if (dg < 96) {
                int row = rowBase + pl;
                int bb = row >> 12, p = row & 4095;
                xraw[((size_t)bb * DI + dg) * Lseq + p] = Tr[dl][pl];
            }
        }
    }
}

// -------------------- generic GEMM C = A * B^T (out_proj) --------------------
__global__ void gemm_abt(const float* __restrict__ A, const float* __restrict__ Bm,
                         float* __restrict__ C, int M, int N, int K) {
    __shared__ __align__(16) float As[32][68];
    __shared__ __align__(16) float Bs[32][68];
    int tid = threadIdx.x;
    int tx = tid & 15, ty = tid >> 4;
    int rowBase = blockIdx.y * 64;
    int colBase = blockIdx.x * 64;
    float acc[4][4];
#pragma unroll
    for (int i = 0; i < 4; i++)
#pragma unroll
        for (int j = 0; j < 4; j++) acc[i][j] = 0.f;

    for (int k0 = 0; k0 < K; k0 += 32) {
#pragma unroll
        for (int pass = 0; pass < 8; pass++) {
            int m = (tid >> 5) + pass * 8;
            int kk = tid & 31;
            As[kk][m] = A[(size_t)(rowBase + m) * K + k0 + kk];
            int nn = colBase + m;
            Bs[kk][m] = (nn < N) ? Bm[(size_t)nn * K + k0 + kk] : 0.f;
        }
        __syncthreads();
#pragma unroll
        for (int kk = 0; kk < 32; kk++) {
            float4 a4 = *reinterpret_cast<const float4*>(&As[kk][ty * 4]);
            float4 b4 = *reinterpret_cast<const float4*>(&Bs[kk][tx * 4]);
            float av[4] = {a4.x, a4.y, a4.z, a4.w};
            float bv[4] = {b4.x, b4.y, b4.z, b4.w};
#pragma unroll
            for (int i = 0; i < 4; i++)
#pragma unroll
                for (int j = 0; j < 4; j++) acc[i][j] = fmaf(av[i], bv[j], acc[i][j]);
        }
        __syncthreads();
    }
    int col = colBase + tx * 4;
    if (col < N) {
#pragma unroll
        for (int i = 0; i < 4; i++) {
            int row = rowBase + ty * 4 + i;
            *reinterpret_cast<float4*>(&C[(size_t)row * N + col]) =
                make_float4(acc[i][0], acc[i][1], acc[i][2], acc[i][3]);
        }
    }
}

// -------------------- depthwise conv3x3 + SiLU (zero-padded halo) --------------------
__global__ void conv_silu(const float* __restrict__ xraw, const float* __restrict__ cw,
                          const float* __restrict__ cb, float* __restrict__ xc,
                          float* __restrict__ xcT) {
    __shared__ float sin_[66][67];
    __shared__ float sout[64][65];
    int bd = blockIdx.x;
    int d = bd % DI;
    const float* plane = xraw + (size_t)bd * Lseq;
    int tid = threadIdx.x;
    // zero halo: rows 0,65 and cols 0,65
    for (int i = tid; i < 66; i += 256) {
        sin_[0][i] = 0.f;
        sin_[65][i] = 0.f;
    }
    for (int i = tid; i < 66; i += 256) {
        sin_[i][0] = 0.f;
        sin_[i][65] = 0.f;
    }
    for (int i = tid; i < 4096; i += 256) sin_[(i >> 6) + 1][(i & 63) + 1] = plane[i];
    float w9[9];
#pragma unroll
    for (int j = 0; j < 9; j++) w9[j] = cw[d * 9 + j];
    float bias = cb[d];
    __syncthreads();
    for (int i = tid; i < 4096; i += 256) {
        int h = i >> 6, w = i & 63;
        float acc = bias;
#pragma unroll
        for (int di = 0; di < 3; di++)
#pragma unroll
            for (int dj = 0; dj < 3; dj++)
                acc = fmaf(w9[di * 3 + dj], sin_[h + di][w + dj], acc);
        float s = acc / (1.f + __expf(-acc));
        sout[h][w] = s;
        xc[(size_t)bd * Lseq + i] = s;
    }
    __syncthreads();
    for (int i = tid; i < 4096; i += 256) {
        int w = i >> 6, h = i & 63;
        xcT[(size_t)bd * Lseq + i] = sout[h][w];
    }
}

// -------------------- x_proj + dt_proj + softplus fused --------------------
#define LT 64
#define WROWS 40
__device__ __forceinline__ float softplusf(float x) {
    return (x > 15.f) ? x : log1pf(__expf(x));
}

__global__ void xproj_kernel(const float* __restrict__ xc, const float* __restrict__ xcT,
                             const float* __restrict__ xpw, const float* __restrict__ dtw,
                             const float* __restrict__ dtb,
                             float* __restrict__ b4, float* __restrict__ c4,
                             float* __restrict__ deltaT, float* __restrict__ duT) {
    __shared__ __align__(16) float Ws[WROWS * 96];   // zero-padded; aliased as sBc after GEMM
    __shared__ float Us[96][LT];
    __shared__ float Dts[DTR][LT];
    __shared__ float Wdt[96 * DTR];
    __shared__ float Bdt[96];
    int bk = blockIdx.y;
    int b = bk >> 2, k = bk & 3;
    int l0 = blockIdx.x * LT;
    int tid = threadIdx.x;
    for (int i = tid; i < WROWS * 96; i += 256)
        Ws[i] = (i < CDIM * 96) ? xpw[k * CDIM * 96 + i] : 0.f;
    for (int i = tid; i < 96 * DTR; i += 256) Wdt[i] = dtw[k * 96 * DTR + i];
    if (tid < 96) Bdt[tid] = dtb[k * 96 + tid];
    const float* src = ((k & 1) ? xcT : xc) + (size_t)b * DI * Lseq;
    bool rev = (k >= 2);
    for (int i = tid; i < 96 * LT; i += 256) {
        int e = i >> 6, li = i & 63;
        int l = l0 + li;
        Us[e][li] = src[(size_t)e * Lseq + (rev ? (Lseq - 1 - l) : l)];
    }
    __syncthreads();
    int lx = tid & 31, cy = tid >> 5;
    float acc[5][2];
#pragma unroll
    for (int j = 0; j < 5; j++) { acc[j][0] = 0.f; acc[j][1] = 0.f; }
#pragma unroll 2
    for (int e4 = 0; e4 < 96; e4 += 4) {
        float4 wv[5];
#pragma unroll
        for (int j = 0; j < 5; j++)
            wv[j] = *reinterpret_cast<const float4*>(&Ws[(cy + 8 * j) * 96 + e4]);
#pragma unroll
        for (int q = 0; q < 4; q++) {
            int e = e4 + q;
            float u0 = Us[e][lx];
            float u1 = Us[e][lx + 32];
#pragma unroll
            for (int j = 0; j < 5; j++) {
                float w = (&wv[j].x)[q];
                acc[j][0] = fmaf(w, u0, acc[j][0]);
                acc[j][1] = fmaf(w, u1, acc[j][1]);
            }
        }
    }
    __syncthreads();   // Ws reads complete; alias as sBc
    float (*sBc)[33] = reinterpret_cast<float (*)[33]>(&Ws[0]);
#pragma unroll
    for (int j = 0; j < 5; j++) {
        int c = cy + 8 * j;
        if (c < DTR) {
            Dts[c][lx] = acc[j][0];
            Dts[c][lx + 32] = acc[j][1];
        } else if (c < CDIM) {
            int cc = c - DTR;                       // 0..31
            int slot = (cc < DS) ? (2 * cc) : (2 * (cc - DS) + 1);
            sBc[lx][slot] = acc[j][0];
            sBc[lx + 32][slot] = acc[j][1];
        }
    }
    __syncthreads();
    // quad-packed copy-out: B4/C4 [l/4][n][4]
    size_t qbase = ((size_t)bk * (Lseq / 4) + (l0 >> 2)) * 64;
#pragma unroll
    for (int pass = 0; pass < 4; pass++) {
        int idx = pass * 256 + tid;
        int l4 = idx >> 6, n = (idx >> 2) & 15, j = idx & 3;
        int l = l4 * 4 + j;
        b4[qbase + idx] = sBc[l][2 * n];
        c4[qbase + idx] = sBc[l][2 * n + 1];
    }
    // delta stage: delta + du (u still live in Us)
#pragma unroll
    for (int o = 0; o < 24; o++) {
        int idx = o * 256 + tid;
        int li = idx & 63, dd = idx >> 6;
        float a = Bdt[dd];
#pragma unroll
        for (int r = 0; r < DTR; r++) a = fmaf(Dts[r][li], Wdt[dd * DTR + r], a);
        float sp = softplusf(a);
        size_t off = ((size_t)bk * DI + dd) * Lseq + l0 + li;
        deltaT[off] = sp;
        duT[off] = sp * Us[dd][li];
    }
}

// -------------------- chunked selective scan (2 states/lane: warp = 4d x 8n) --------------------
// chain index (matches scanB): bk*1536 + d*16 + n

__global__ void __launch_bounds__(256, 6)
scanA_kernel(const float* __restrict__ deltaT, const float* __restrict__ duT,
             const float* __restrict__ b4,
             const float* __restrict__ A_logs,
             float* __restrict__ hend, float* __restrict__ pprod) {
    int w = blockIdx.x * 8 + (threadIdx.x >> 5);   // 24576 warps
    int lane = threadIdx.x & 31;
    int bk = w / (24 * NCH);
    int rem = w % (24 * NCH);
    int chunk = rem / 24;
    int dg = rem % 24;
    int k = bk & 3;
    int nq = lane & 7;
    int dq = lane >> 3;
    int d = dg * 4 + dq;
    float Av0 = -__expf(A_logs[(k * DI + d) * DS + nq]) * L2E;
    float Av1 = -__expf(A_logs[(k * DI + d) * DS + nq + 8]) * L2E;
    int l0 = chunk * CH;

    const float4* drow = reinterpret_cast<const float4*>(deltaT + ((size_t)bk * DI + d) * Lseq + l0);
    const float4* durow = reinterpret_cast<const float4*>(duT + ((size_t)bk * DI + d) * Lseq + l0);
    const float4* brow = reinterpret_cast<const float4*>(b4) + ((size_t)bk * (Lseq / 4) + (l0 >> 2)) * 16 + nq;

    float h0 = 0.f, h1 = 0.f, S = 0.f;
#pragma unroll 2
    for (int g = 0; g < CH / 4; g++) {
        float4 dl4 = __ldg(drow + g);
        float4 du4 = __ldg(durow + g);
        float4 B0 = __ldg(brow + g * 16);
        float4 B1 = __ldg(brow + g * 16 + 8);
        S += (dl4.x + dl4.y) + (dl4.z + dl4.w);
        float dA;
        dA = ex2f(dl4.x * Av0); h0 = fmaf(h0, dA, du4.x * B0.x);
        dA = ex2f(dl4.x * Av1); h1 = fmaf(h1, dA, du4.x * B1.x);
        dA = ex2f(dl4.y * Av0); h0 = fmaf(h0, dA, du4.y * B0.y);
        dA = ex2f(dl4.y * Av1); h1 = fmaf(h1, dA, du4.y * B1.y);
        dA = ex2f(dl4.z * Av0); h0 = fmaf(h0, dA, du4.z * B0.z);
        dA = ex2f(dl4.z * Av1); h1 = fmaf(h1, dA, du4.z * B1.z);
        dA = ex2f(dl4.w * Av0); h0 = fmaf(h0, dA, du4.w * B0.w);
        dA = ex2f(dl4.w * Av1); h1 = fmaf(h1, dA, du4.w * B1.w);
    }
    int cbase = chunk * NCHAIN + bk * 1536 + d * 16 + nq;
    hend[cbase] = h0;
    hend[cbase + 8] = h1;
    pprod[cbase] = ex2f(Av0 * S);
    pprod[cbase + 8] = ex2f(Av1 * S);
}

__global__ void scanB_kernel(const float* __restrict__ hend, const float* __restrict__ pprod,
                             float* __restrict__ hinit) {
    int chain = blockIdx.x * 256 + threadIdx.x;
    float H = 0.f;
#pragma unroll 8
    for (int c = 0; c < NCH; c++) {
        int idx = c * NCHAIN + chain;
        hinit[idx] = H;
        H = fmaf(H, pprod[idx], hend[idx]);
    }
}

__global__ void __launch_bounds__(256, 6)
scanC_kernel(const float* __restrict__ deltaT, const float* __restrict__ duT,
             const float* __restrict__ b4, const float* __restrict__ c4,
             const float* __restrict__ A_logs,
             const float* __restrict__ hinit, float* __restrict__ ysd) {
    int w = blockIdx.x * 8 + (threadIdx.x >> 5);   // 24576 warps
    int lane = threadIdx.x & 31;
    int bk = w / (24 * NCH);
    int rem = w % (24 * NCH);
    int chunk = rem / 24;
    int dg = rem % 24;
    int k = bk & 3;
    int nq = lane & 7;
    int dq = lane >> 3;
    int d = dg * 4 + dq;
    float Av0 = -__expf(A_logs[(k * DI + d) * DS + nq]) * L2E;
    float Av1 = -__expf(A_logs[(k * DI + d) * DS + nq + 8]) * L2E;
    int l0 = chunk * CH;

    const float4* drow = reinterpret_cast<const float4*>(deltaT + ((size_t)bk * DI + d) * Lseq + l0);
    const float4* durow = reinterpret_cast<const float4*>(duT + ((size_t)bk * DI + d) * Lseq + l0);
    const float4* brow = reinterpret_cast<const float4*>(b4) + ((size_t)bk * (Lseq / 4) + (l0 >> 2)) * 16 + nq;
    const float4* crow = reinterpret_cast<const float4*>(c4) + ((size_t)bk * (Lseq / 4) + (l0 >> 2)) * 16 + nq;

    int pstart, pstep;
    if (k == 0)      { pstart = l0;            pstep = 1;   }
    else if (k == 1) { pstart = chunk;         pstep = 64;  }
    else if (k == 2) { pstart = Lseq - 1 - l0; pstep = -1;  }
    else             { pstart = 4095 - chunk;  pstep = -64; }
    float* ybase = ysd + ((size_t)bk * DI + d) * Lseq + pstart;
    int ridx = ((nq & 4) ? 2 : 0) + ((nq & 2) ? 1 : 0);
    bool writer = ((nq & 1) == 0);

    int cbase = chunk * NCHAIN + bk * 1536 + d * 16 + nq;
    float h0 = hinit[cbase];
    float h1 = hinit[cbase + 8];
    const unsigned FULL = 0xffffffffu;

#pragma unroll 2
    for (int g = 0; g < CH / 4; g++) {
        float4 dl4 = __ldg(drow + g);
        float4 du4 = __ldg(durow + g);
        float4 B0 = __ldg(brow + g * 16);
        float4 B1 = __ldg(brow + g * 16 + 8);
        float4 C0 = __ldg(crow + g * 16);
        float4 C1 = __ldg(crow + g * 16 + 8);
        float dls[4] = {dl4.x, dl4.y, dl4.z, dl4.w};
        float dus[4] = {du4.x, du4.y, du4.z, du4.w};
        float B0s[4] = {B0.x, B0.y, B0.z, B0.w};
        float B1s[4] = {B1.x, B1.y, B1.z, B1.w};
        float C0s[4] = {C0.x, C0.y, C0.z, C0.w};
        float C1s[4] = {C1.x, C1.y, C1.z, C1.w};
        float acc[4];
#pragma unroll
        for (int j = 0; j < 4; j++) {
            float dA0 = ex2f(dls[j] * Av0);
            h0 = fmaf(h0, dA0, dus[j] * B0s[j]);
            float dA1 = ex2f(dls[j] * Av1);
            h1 = fmaf(h1, dA1, dus[j] * B1s[j]);
            float p = h0 * C0s[j];
            acc[j] = fmaf(h1, C1s[j], p);
        }
        bool up4 = (nq & 4);
#pragma unroll
        for (int j = 0; j < 2; j++) {
            float mine = up4 ? acc[j + 2] : acc[j];
            float oth  = up4 ? acc[j] : acc[j + 2];
            acc[j] = mine + __shfl_xor_sync(FULL, oth, 4);
        }
        {
            bool up2 = (nq & 2);
            float mine = up2 ? acc[1] : acc[0];
            float oth  = up2 ? acc[0] : acc[1];
            acc[0] = mine + __shfl_xor_sync(FULL, oth, 2);
        }
        acc[0] += __shfl_xor_sync(FULL, acc[0], 1);
        if (writer) ybase[(g * 4 + ridx) * pstep] = acc[0];
    }
}

// -------------------- combine 4 dirs + D*u skip + LayerNorm + SiLU gate --------------------
__global__ void combine_ln_gate(const float* __restrict__ ysd, const float* __restrict__ xc,
                                const float* __restrict__ dsp, const float* __restrict__ xz,
                                const float* __restrict__ nw, const float* __restrict__ nb,
                                float* __restrict__ yg) {
    __shared__ float s[96][33];
    int b = blockIdx.y;
    int p0 = blockIdx.x * 32;
    int tid = threadIdx.x;
    int px = tid & 31, drow = tid >> 5;
    const float* base = ysd + (size_t)(b * 4) * DI * Lseq + p0 + px;
#pragma unroll
    for (int j = 0; j < 12; j++) {
        int dd = drow + j * 8;
        const float* r = base + (size_t)dd * Lseq;
        float dsum = dsp[dd] + dsp[DI + dd] + dsp[2 * DI + dd] + dsp[3 * DI + dd];
        float xcv = xc[((size_t)b * DI + dd) * Lseq + p0 + px];
        float v = r[0] + r[DI * Lseq] + r[2 * DI * Lseq] + r[3 * DI * Lseq];
        s[dd][px] = fmaf(dsum, xcv, v);
    }
    __syncthreads();
    int p = tid >> 3, rr = tid & 7;
    float s1 = 0.f, s2 = 0.f;
#pragma unroll
    for (int m = 0; m < 12; m++) {
        float v = s[rr + m * 8][p];
        s1 += v;
        s2 = fmaf(v, v, s2);
    }
#pragma unroll
    for (int o = 4; o >= 1; o >>= 1) {
        s1 += __shfl_xor_sync(0xffffffffu, s1, o);
        s2 += __shfl_xor_sync(0xffffffffu, s2, o);
    }
    float mu = s1 * (1.f / 96.f);
    float var = s2 * (1.f / 96.f) - mu * mu;
    float rinv = rsqrtf(var + 1e-5f);
    size_t rowout = ((size_t)b * Lseq + p0 + p);
#pragma unroll
    for (int m = 0; m < 12; m++) {
        int dd = rr + m * 8;
        float v = s[dd][p];
        float yn = (v - mu) * rinv * nw[dd] + nb[dd];
        float zv = xz[rowout * 192 + 96 + dd];
        yg[rowout * DI + dd] = yn * (zv / (1.f + __expf(-zv)));
    }
}

// -------------------- host launcher --------------------
extern "C" void kernel_launch(void* const* d_in, const int* in_sizes, int n_in,
                              void* d_out, int out_size) {
    const float* x     = (const float*)d_in[0];
    const float* inw   = (const float*)d_in[1];
    const float* convw = (const float*)d_in[2];
    const float* convb = (const float*)d_in[3];
    const float* xpw   = (const float*)d_in[4];
    const float* dtw   = (const float*)d_in[5];
    const float* dtb   = (const float*)d_in[6];
    const float* alog  = (const float*)d_in[7];
    const float* dsp   = (const float*)d_in[8];
    const float* nw    = (const float*)d_in[9];
    const float* nb    = (const float*)d_in[10];
    const float* ow    = (const float*)d_in[11];
    float* out = (float*)d_out;

    float *xz, *xraw, *xc, *xcT, *b4, *c4, *deltaT, *duT, *ysd, *yg, *hend, *pprod, *hinit;
    cudaGetSymbolAddress((void**)&xz, g_xz);
    cudaGetSymbolAddress((void**)&xraw, g_xraw);
    cudaGetSymbolAddress((void**)&xc, g_xc);
    cudaGetSymbolAddress((void**)&xcT, g_xcT);
    cudaGetSymbolAddress((void**)&b4, g_b4);
    cudaGetSymbolAddress((void**)&c4, g_c4);
    cudaGetSymbolAddress((void**)&deltaT, g_deltaT);
    cudaGetSymbolAddress((void**)&duT, g_duT);
    cudaGetSymbolAddress((void**)&ysd, g_ysd);
    cudaGetSymbolAddress((void**)&yg, g_yg);
    cudaGetSymbolAddress((void**)&hend, g_hend);
    cudaGetSymbolAddress((void**)&pprod, g_pprod);
    cudaGetSymbolAddress((void**)&hinit, g_hinit);

    gemm_in_proj<<<dim3(3, 256), 256>>>(x, inw, xz, xraw);
    conv_silu<<<Bn_ * DI, 256>>>(xraw, convw, convb, xc, xcT);
    xproj_kernel<<<dim3(Lseq / LT, 16), 256>>>(xc, xcT, xpw, dtw, dtb, b4, c4, deltaT, duT);
    scanA_kernel<<<16 * 24 * NCH / 8, 256>>>(deltaT, duT, b4, alog, hend, pprod);
    scanB_kernel<<<NCHAIN / 256, 256>>>(hend, pprod, hinit);
    scanC_kernel<<<16 * 24 * NCH / 8, 256>>>(deltaT, duT, b4, c4, alog, hinit, ysd);
    combine_ln_gate<<<dim3(Lseq / 32, Bn_), 256>>>(ysd, xc, dsp, xz, nw, nb, yg);
    gemm_abt<<<dim3(2, 256), 256>>>(yg, ow, out, Bn_ * Lseq, 96, 96);
}